// round 14
// baseline (speedup 1.0000x reference)
#include <cuda_runtime.h>
#include <cuda_bf16.h>
#include <cuda_fp16.h>
#include <cstdint>

#define DM 512
#define SN 64
#define NBATCH 4
#define SEQ 2048
#define M_TOT (NBATCH*SEQ)   // 8192
#define KDIM 512

// ---------------- scratch (no runtime allocation allowed) ----------------
__device__ float g_ut[M_TOT * DM];       // u transposed [b, d, t] (fp32)
__device__ float g_gate[M_TOT * DM];     // sigmoid gate [bt, d]
__device__ __half g_xh[M_TOT * DM];
__device__ __half g_xl[M_TOT * DM];
__device__ __half g_yht[M_TOT * DM];     // y hi, transposed [b, d, t]
__device__ __half g_ylt[M_TOT * DM];     // y lo, transposed
__device__ __half g_wi[DM * DM];
__device__ __half g_wg[DM * DM];
__device__ __half g_wo[DM * DM];
__device__ float g_ar[DM * SN];
__device__ float g_ai[DM * SN];
__device__ float g_cb[DM * SN];

// ---------------- f32x2 packed helpers ------------------------------------
__device__ __forceinline__ unsigned long long pk2(float a, float b) {
    unsigned long long r;
    asm("mov.b64 %0, {%1, %2};" : "=l"(r) : "f"(a), "f"(b));
    return r;
}
__device__ __forceinline__ void upk2(unsigned long long v, float& a, float& b) {
    asm("mov.b64 {%0, %1}, %2;" : "=f"(a), "=f"(b) : "l"(v));
}
__device__ __forceinline__ unsigned long long fma2(unsigned long long a,
                                                   unsigned long long b,
                                                   unsigned long long c) {
    unsigned long long r;
    asm("fma.rn.f32x2 %0, %1, %2, %3;" : "=l"(r) : "l"(a), "l"(b), "l"(c));
    return r;
}
__device__ __forceinline__ unsigned long long mul2(unsigned long long a,
                                                   unsigned long long b) {
    unsigned long long r;
    asm("mul.rn.f32x2 %0, %1, %2;" : "=l"(r) : "l"(a), "l"(b));
    return r;
}

// ---------------- parameter precompute -----------------------------------
__global__ void param_kernel(const float* __restrict__ log_A_real,
                             const float* __restrict__ A_imag,
                             const float* __restrict__ B_p,
                             const float* __restrict__ C_p,
                             const float* __restrict__ log_dt)
{
    int idx = blockIdx.x * blockDim.x + threadIdx.x;
    if (idx >= DM * SN) return;
    int d = idx / SN;
    float dt  = expf(log_dt[d]);
    float are = -expf(log_A_real[idx]);
    float aim = A_imag[idx];
    float r = expf(are * dt);
    float s, c;
    sincosf(aim * dt, &s, &c);
    g_ar[idx] = r * c;
    g_ai[idx] = r * s;
    g_cb[idx] = C_p[idx] * B_p[idx] * dt;
}

// ---------------- fp32 -> fp16 split of x + fp16 convert of 3 weights ------
__global__ void prep_kernel(const float* __restrict__ x,
                            const float* __restrict__ w0, const float* __restrict__ w1,
                            const float* __restrict__ w2,
                            __half* __restrict__ xh, __half* __restrict__ xl,
                            __half* __restrict__ o0, __half* __restrict__ o1,
                            __half* __restrict__ o2)
{
    int i = blockIdx.x * blockDim.x + threadIdx.x;
    const int NX = M_TOT * DM;
    if (i < NX) {
        float v = x[i];
        __half h = __float2half(v);
        xh[i] = h;
        xl[i] = __float2half(v - __half2float(h));
    } else {
        int j = i - NX;
        if (j >= 3 * DM * DM) return;
        int which = j / (DM * DM);
        int k = j - which * (DM * DM);
        const float* src = (which == 0) ? w0 : (which == 1) ? w1 : w2;
        __half* dst      = (which == 0) ? o0 : (which == 1) ? o1 : o2;
        dst[k] = __float2half(src[k]);
    }
}

// ============================================================================
// fp16 2-pass mma.sync GEMM body (A row-major [m,k] in gmem).
// Tile 128x128, 256 threads (8 warps 2x4), 2-stage.
// MODE 0: u -> written TRANSPOSED to g_ut[b,d,t] via smem.
// MODE 1: sigmoid(acc + bias) -> C.
// ============================================================================
#define GBM 128
#define GBN 128
#define GBK 32
#define RSTRIDE 40
#define PIECE_ELEMS (GBM * RSTRIDE)           // 5120 fp16
#define STAGE_ELEMS (3 * PIECE_ELEMS)         // Ah, Al, B = 15360
#define GEMM_SMEM (2 * STAGE_ELEMS * 2)       // 61440 B
#define SCAN_SMEM (8 * 32 * 33 * 4)           // 33792 B (float partials)

__device__ __forceinline__ void ldm_x4(uint32_t& r0, uint32_t& r1,
                                       uint32_t& r2, uint32_t& r3, uint32_t addr)
{
    asm volatile("ldmatrix.sync.aligned.m8n8.x4.shared.b16 {%0,%1,%2,%3}, [%4];"
                 : "=r"(r0), "=r"(r1), "=r"(r2), "=r"(r3) : "r"(addr));
}

__device__ __forceinline__ void ldm_x4_t(uint32_t& r0, uint32_t& r1,
                                         uint32_t& r2, uint32_t& r3, uint32_t addr)
{
    asm volatile("ldmatrix.sync.aligned.m8n8.x4.trans.shared.b16 {%0,%1,%2,%3}, [%4];"
                 : "=r"(r0), "=r"(r1), "=r"(r2), "=r"(r3) : "r"(addr));
}

__device__ __forceinline__ void mma16816(float* c, const uint32_t* a,
                                         uint32_t b0, uint32_t b1)
{
    asm volatile(
        "mma.sync.aligned.m16n8k16.row.col.f32.f16.f16.f32 "
        "{%0,%1,%2,%3}, {%4,%5,%6,%7}, {%8,%9}, {%0,%1,%2,%3};"
        : "+f"(c[0]), "+f"(c[1]), "+f"(c[2]), "+f"(c[3])
        : "r"(a[0]), "r"(a[1]), "r"(a[2]), "r"(a[3]), "r"(b0), "r"(b1));
}

#define CP16(dst, src) \
    asm volatile("cp.async.cg.shared.global [%0], [%1], 16;" :: "r"(dst), "l"(src))
#define CP_COMMIT() asm volatile("cp.async.commit_group;")
#define CP_WAIT1()  asm volatile("cp.async.wait_group 1;")
#define CP_WAIT0()  asm volatile("cp.async.wait_group 0;")

template<int MODE>
__device__ __forceinline__ void gemm_body(
    int bx, int by, char* smem_raw,
    const __half* __restrict__ Ah, const __half* __restrict__ Al,
    const __half* __restrict__ B,
    float* __restrict__ C,
    const float* __restrict__ bias)
{
    __half* smem = reinterpret_cast<__half*>(smem_raw);
    const uint32_t sbase = (uint32_t)__cvta_generic_to_shared(smem);

    const int tid  = threadIdx.x;
    const int lane = tid & 31;
    const int warp = tid >> 5;
    const int wm   = warp & 1;
    const int wn   = warp >> 1;
    const int m0   = by * GBM;
    const int n0   = bx * GBN;

    const int arow = tid >> 2;        // 0..63
    const int ac   = (tid & 3) * 8;

    const __half* gAh0 = Ah + (size_t)(m0 + arow)      * KDIM + ac;
    const __half* gAh1 = Ah + (size_t)(m0 + arow + 64) * KDIM + ac;
    const __half* gAl0 = Al + (size_t)(m0 + arow)      * KDIM + ac;
    const __half* gAl1 = Al + (size_t)(m0 + arow + 64) * KDIM + ac;
    const __half* gB0  = B  + (size_t)(n0 + arow)      * KDIM + ac;
    const __half* gB1  = B  + (size_t)(n0 + arow + 64) * KDIM + ac;

    const uint32_t dR0 = (uint32_t)((arow        * RSTRIDE + ac) * 2);
    const uint32_t dR1 = (uint32_t)(((arow + 64) * RSTRIDE + ac) * 2);

    auto load_stage = [&](int s, int kk) {
        uint32_t sb = sbase + (uint32_t)(s * STAGE_ELEMS * 2);
        uint32_t aH = sb;
        uint32_t aL = sb + PIECE_ELEMS * 2;
        uint32_t bB = sb + 2 * PIECE_ELEMS * 2;
        CP16(aH + dR0, gAh0 + kk);
        CP16(aH + dR1, gAh1 + kk);
        CP16(aL + dR0, gAl0 + kk);
        CP16(aL + dR1, gAl1 + kk);
        CP16(bB + dR0, gB0  + kk);
        CP16(bB + dR1, gB1  + kk);
    };

    float acc[4][4][4];
    #pragma unroll
    for (int i = 0; i < 4; i++)
        #pragma unroll
        for (int j = 0; j < 4; j++)
            #pragma unroll
            for (int k = 0; k < 4; k++) acc[i][j][k] = 0.f;

    load_stage(0, 0);   CP_COMMIT();
    load_stage(1, GBK); CP_COMMIT();

    const int grp = lane >> 3;
    const int rin = lane & 7;
    const int rowsel = (grp & 1) * 8 + rin;
    const int colsel = (grp >> 1) * 8;

    const int NKC = KDIM / GBK;        // 16
    for (int kc = 0; kc < NKC; kc++) {
        CP_WAIT1();
        __syncthreads();

        const int s = kc & 1;
        const uint32_t sb = sbase + (uint32_t)(s * STAGE_ELEMS * 2);
        const uint32_t aH = sb;
        const uint32_t aL = sb + PIECE_ELEMS * 2;
        const uint32_t bB = sb + 2 * PIECE_ELEMS * 2;

        #pragma unroll
        for (int ks = 0; ks < 2; ks++) {
            const int kb = ks * 16 + colsel;

            uint32_t bh[2][4];
            #pragma unroll
            for (int p = 0; p < 2; p++) {
                uint32_t off = (uint32_t)(((wn * 32 + p * 16 + rowsel) * RSTRIDE + kb) * 2);
                ldm_x4(bh[p][0], bh[p][1], bh[p][2], bh[p][3], bB + off);
            }

            #pragma unroll
            for (int mt = 0; mt < 4; mt++) {
                uint32_t off = (uint32_t)(((wm * 64 + mt * 16 + rowsel) * RSTRIDE + kb) * 2);
                uint32_t ah[4], al[4];
                ldm_x4(ah[0], ah[1], ah[2], ah[3], aH + off);
                ldm_x4(al[0], al[1], al[2], al[3], aL + off);

                #pragma unroll
                for (int nt = 0; nt < 4; nt++) {
                    const int p = nt >> 1, o = nt & 1;
                    mma16816(acc[mt][nt], ah, bh[p][0 + o], bh[p][2 + o]);
                }
                #pragma unroll
                for (int nt = 0; nt < 4; nt++) {
                    const int p = nt >> 1, o = nt & 1;
                    mma16816(acc[mt][nt], al, bh[p][0 + o], bh[p][2 + o]);
                }
            }
        }
        __syncthreads();
        if (kc + 2 < NKC) load_stage(s, (kc + 2) * GBK);
        CP_COMMIT();
    }

    const int r   = lane >> 2;
    const int cp2 = (lane & 3) * 2;

    if (MODE == 0) {
        // ---- transposed epilogue: u tile -> g_ut[b, d, t] via smem ----
        CP_WAIT0();
        __syncthreads();
        float* tsm = reinterpret_cast<float*>(smem);   // 64 cols x 132 stride
        const int bb = m0 / SEQ;
        const int t0 = m0 % SEQ;
        #pragma unroll
        for (int round = 0; round < 2; round++) {
            if ((wn >> 1) == round) {
                const int colb = (wn & 1) * 32;
                #pragma unroll
                for (int mt = 0; mt < 4; mt++)
                    #pragma unroll
                    for (int nt = 0; nt < 4; nt++)
                        #pragma unroll
                        for (int h = 0; h < 2; h++) {
                            const int row = wm * 64 + mt * 16 + r + h * 8;
                            const int col = colb + nt * 8 + cp2;
                            tsm[col * 132 + row]       = acc[mt][nt][2 * h + 0];
                            tsm[(col + 1) * 132 + row] = acc[mt][nt][2 * h + 1];
                        }
            }
            __syncthreads();
            const int d0r = n0 + round * 64;
            #pragma unroll
            for (int i = 0; i < 8; i++) {
                const int idx = tid + i * 256;
                const int c   = idx >> 5;
                const int tq  = idx & 31;
                float4 v = *(float4*)&tsm[c * 132 + tq * 4];
                *(float4*)&g_ut[(size_t)(bb * DM + d0r + c) * SEQ + t0 + tq * 4] = v;
            }
            __syncthreads();
        }
        return;
    }

    // MODE 1: sigmoid epilogue
    #pragma unroll
    for (int mt = 0; mt < 4; mt++) {
        #pragma unroll
        for (int nt = 0; nt < 4; nt++) {
            const int col  = n0 + wn * 32 + nt * 8 + cp2;
            const int row0 = m0 + wm * 64 + mt * 16 + r;
            #pragma unroll
            for (int h = 0; h < 2; h++) {
                const int row = row0 + h * 8;
                const size_t off = (size_t)row * DM + col;
                float v0 = acc[mt][nt][2 * h + 0];
                float v1 = acc[mt][nt][2 * h + 1];
                v0 = 1.f / (1.f + __expf(-(v0 + bias[col + 0])));
                v1 = 1.f / (1.f + __expf(-(v1 + bias[col + 1])));
                *(float2*)&C[off] = make_float2(v0, v1);
            }
        }
    }
}

// ============================================================================
// out-projection GEMM with A loaded TRANSPOSED from g_yht/g_ylt [b,d,t]
// via ldmatrix.trans — no separate transpose kernel needed.
// ============================================================================
#define RS2 136
#define A2_ELEMS (32 * RS2)                    // 4352
#define STAGE2_ELEMS (2 * A2_ELEMS + PIECE_ELEMS)   // 13824
#define GEMM2_SMEM (2 * STAGE2_ELEMS * 2)      // 55296 B

__global__ __launch_bounds__(256, 2) void gemm_out_kernel(
    const __half* __restrict__ Aht, const __half* __restrict__ Alt,
    const __half* __restrict__ B, float* __restrict__ C,
    const float* __restrict__ xres, const float* __restrict__ gate)
{
    extern __shared__ char dsm[];
    __half* smem = reinterpret_cast<__half*>(dsm);
    const uint32_t sbase = (uint32_t)__cvta_generic_to_shared(smem);

    const int tid  = threadIdx.x;
    const int lane = tid & 31;
    const int warp = tid >> 5;
    const int wm   = warp & 1;
    const int wn   = warp >> 1;
    const int m0   = blockIdx.y * GBM;
    const int n0   = blockIdx.x * GBN;
    const int bb   = m0 / SEQ;
    const int t0   = m0 % SEQ;

    const int r16 = tid >> 4;         // 0..15
    const int c16 = (tid & 15) * 8;   // fp16 offset of 16B chunk
    const int arow = tid >> 2;
    const int ac   = (tid & 3) * 8;
    const __half* gB0 = B + (size_t)(n0 + arow)      * KDIM + ac;
    const __half* gB1 = B + (size_t)(n0 + arow + 64) * KDIM + ac;
    const uint32_t dR0 = (uint32_t)((arow        * RSTRIDE + ac) * 2);
    const uint32_t dR1 = (uint32_t)(((arow + 64) * RSTRIDE + ac) * 2);

    auto load_stage = [&](int s, int kc) {
        const int k0 = kc * GBK;
        uint32_t sb = sbase + (uint32_t)(s * STAGE2_ELEMS * 2);
        uint32_t aH = sb;
        uint32_t aL = sb + A2_ELEMS * 2;
        uint32_t bB = sb + 2 * A2_ELEMS * 2;
        const size_t e0 = (size_t)(bb * DM + k0 + r16)      * SEQ + t0 + c16;
        const size_t e1 = (size_t)(bb * DM + k0 + r16 + 16) * SEQ + t0 + c16;
        CP16(aH + (uint32_t)((r16        * RS2 + c16) * 2), Aht + e0);
        CP16(aH + (uint32_t)(((r16 + 16) * RS2 + c16) * 2), Aht + e1);
        CP16(aL + (uint32_t)((r16        * RS2 + c16) * 2), Alt + e0);
        CP16(aL + (uint32_t)(((r16 + 16) * RS2 + c16) * 2), Alt + e1);
        CP16(bB + dR0, gB0 + k0);
        CP16(bB + dR1, gB1 + k0);
    };

    float acc[4][4][4];
    #pragma unroll
    for (int i = 0; i < 4; i++)
        #pragma unroll
        for (int j = 0; j < 4; j++)
            #pragma unroll
            for (int k = 0; k < 4; k++) acc[i][j][k] = 0.f;

    load_stage(0, 0); CP_COMMIT();
    load_stage(1, 1); CP_COMMIT();

    const int grp = lane >> 3;
    const int rin = lane & 7;
    const int rowsel = (grp & 1) * 8 + rin;
    const int colsel = (grp >> 1) * 8;
    const int akrow = (grp >> 1) * 8 + rin;
    const int amoff = (grp & 1) * 8;

    const int NKC = KDIM / GBK;        // 16
    for (int kc = 0; kc < NKC; kc++) {
        CP_WAIT1();
        __syncthreads();

        const int s = kc & 1;
        const uint32_t sb = sbase + (uint32_t)(s * STAGE2_ELEMS * 2);
        const uint32_t aH = sb;
        const uint32_t aL = sb + A2_ELEMS * 2;
        const uint32_t bB = sb + 2 * A2_ELEMS * 2;

        #pragma unroll
        for (int ks = 0; ks < 2; ks++) {
            const int kb = ks * 16;

            uint32_t bh[2][4];
            #pragma unroll
            for (int p = 0; p < 2; p++) {
                uint32_t off = (uint32_t)(((wn * 32 + p * 16 + rowsel) * RSTRIDE + kb + colsel) * 2);
                ldm_x4(bh[p][0], bh[p][1], bh[p][2], bh[p][3], bB + off);
            }

            #pragma unroll
            for (int mt = 0; mt < 4; mt++) {
                const int mbase = wm * 64 + mt * 16;
                uint32_t off = (uint32_t)(((kb + akrow) * RS2 + mbase + amoff) * 2);
                uint32_t ah[4], al[4];
                ldm_x4_t(ah[0], ah[1], ah[2], ah[3], aH + off);
                ldm_x4_t(al[0], al[1], al[2], al[3], aL + off);

                #pragma unroll
                for (int nt = 0; nt < 4; nt++) {
                    const int p = nt >> 1, o = nt & 1;
                    mma16816(acc[mt][nt], ah, bh[p][0 + o], bh[p][2 + o]);
                }
                #pragma unroll
                for (int nt = 0; nt < 4; nt++) {
                    const int p = nt >> 1, o = nt & 1;
                    mma16816(acc[mt][nt], al, bh[p][0 + o], bh[p][2 + o]);
                }
            }
        }
        __syncthreads();
        if (kc + 2 < NKC) load_stage(s, kc + 2);
        CP_COMMIT();
    }

    const int r   = lane >> 2;
    const int cp2 = (lane & 3) * 2;
    #pragma unroll
    for (int mt = 0; mt < 4; mt++) {
        #pragma unroll
        for (int nt = 0; nt < 4; nt++) {
            const int col  = n0 + wn * 32 + nt * 8 + cp2;
            const int row0 = m0 + wm * 64 + mt * 16 + r;
            #pragma unroll
            for (int h = 0; h < 2; h++) {
                const int row = row0 + h * 8;
                const size_t off = (size_t)row * DM + col;
                float v0 = acc[mt][nt][2 * h + 0];
                float v1 = acc[mt][nt][2 * h + 1];
                float2 xv = *(const float2*)&xres[off];
                float2 gv = *(const float2*)&gate[off];
                v0 = xv.x + gv.x * v0;
                v1 = xv.y + gv.y * v1;
                *(float2*)&C[off] = make_float2(v0, v1);
            }
        }
    }
}

// ---------------- S4D scan kernel (chain-shortened, conflict-free) ---------
// Per 8-step chunk: prefetch u broadcasts and cbu = cb*(u,u) off the critical
// path. Per-step chain is then only 2 dependent packed FMAs.
__global__ __launch_bounds__(256, 2) void scan_kernel(const float* __restrict__ D_p)
{
    extern __shared__ char dsm[];
    const int lane = threadIdx.x & 31;
    const int wrp  = threadIdx.x >> 5;
    const int sidx = blockIdx.x;                 // 0..255
    const int b    = sidx >> 6;                  // 0..3
    const int d    = (sidx & 63) * 8 + wrp;
    float* spw = reinterpret_cast<float*>(dsm) + wrp * (32 * 33);

    const int base = d * SN;
    const unsigned long long ar2  = pk2(g_ar[base + lane],  g_ar[base + 32 + lane]);
    const unsigned long long ai2  = pk2(g_ai[base + lane],  g_ai[base + 32 + lane]);
    const unsigned long long nai2 = pk2(-g_ai[base + lane], -g_ai[base + 32 + lane]);
    const unsigned long long cb2  = pk2(g_cb[base + lane],  g_cb[base + 32 + lane]);
    const float Dp  = D_p[d];

    const float* up = g_ut + (size_t)(b * DM + d) * SEQ;
    __half* yh = g_yht + (size_t)(b * DM + d) * SEQ;
    __half* yl = g_ylt + (size_t)(b * DM + d) * SEQ;

    unsigned long long gr2 = 0ull, gi2 = 0ull;
    float ucur = up[lane];

    const int NT = SEQ / 32;
    for (int tt = 0; tt < NT; tt++) {
        float unext = 0.f;
        if (tt + 1 < NT) unext = up[(tt + 1) * 32 + lane];

        #pragma unroll
        for (int c = 0; c < 4; c++) {
            // prefetch 8 broadcasts + cbu products (independent of state)
            unsigned long long cbu[8];
            #pragma unroll
            for (int j = 0; j < 8; j++) {
                float uj = __shfl_sync(0xffffffffu, ucur, c * 8 + j);
                cbu[j] = mul2(cb2, pk2(uj, uj));
            }
            #pragma unroll
            for (int j = 0; j < 8; j++) {
                unsigned long long t  = fma2(nai2, gi2, cbu[j]);
                unsigned long long ni = fma2(ai2, gr2, mul2(ar2, gi2));
                unsigned long long nr = fma2(ar2, gr2, t);
                gr2 = nr; gi2 = ni;
                float s0, s1;
                upk2(nr, s0, s1);
                spw[(c * 8 + j) * 33 + lane] = s0 + s1;
            }
        }
        __syncwarp();

        // lane L sums 32 floats at stride 33 (conflict-free), 4-way ILP tree
        const float* rp = spw + lane * 33;
        float a0 = rp[0], a1 = rp[1], a2 = rp[2], a3 = rp[3];
        #pragma unroll
        for (int k2 = 4; k2 < 32; k2 += 4) {
            a0 += rp[k2 + 0];
            a1 += rp[k2 + 1];
            a2 += rp[k2 + 2];
            a3 += rp[k2 + 3];
        }
        float acc = fmaf(Dp, ucur, (a0 + a1) + (a2 + a3));

        const int oidx = tt * 32 + lane;
        __half h = __float2half(acc);
        yh[oidx] = h;
        yl[oidx] = __float2half(acc - __half2float(h));
        __syncwarp();

        ucur = unext;
    }
}

// ---------------- fused u + gate projection (all blocks tensor-bound) ------
// blocks [0,256): u tiles (MODE 0, transposed epilogue)
// blocks [256,512): gate tiles (MODE 1, sigmoid epilogue)
__global__ __launch_bounds__(256, 2) void proj_kernel(
    const __half* __restrict__ xh, const __half* __restrict__ xl,
    const __half* __restrict__ wi, const __half* __restrict__ wg,
    float* __restrict__ pg, const float* __restrict__ bias)
{
    extern __shared__ char dsm[];
    if (blockIdx.x < 256) {
        const int g = blockIdx.x;
        gemm_body<0>(g & 3, g >> 2, dsm, xh, xl, wi, nullptr, nullptr);
    } else {
        const int g = blockIdx.x - 256;
        gemm_body<1>(g & 3, g >> 2, dsm, xh, xl, wg, pg, bias);
    }
}

// ---------------- launch --------------------------------------------------
extern "C" void kernel_launch(void* const* d_in, const int* in_sizes, int n_in,
                              void* d_out, int out_size)
{
    const float* x          = (const float*)d_in[0];
    const float* log_A_real = (const float*)d_in[1];
    const float* A_imag     = (const float*)d_in[2];
    const float* B_p        = (const float*)d_in[3];
    const float* C_p        = (const float*)d_in[4];
    const float* D_p        = (const float*)d_in[5];
    const float* log_dt     = (const float*)d_in[6];
    const float* W_in       = (const float*)d_in[7];
    const float* W_out      = (const float*)d_in[8];
    const float* W_gate     = (const float*)d_in[9];
    const float* b_gate     = (const float*)d_in[10];
    float* out = (float*)d_out;

    float *pg;
    __half *xh, *xl, *yht, *ylt, *wi, *wg, *wo;
    cudaGetSymbolAddress((void**)&pg,  g_gate);
    cudaGetSymbolAddress((void**)&xh,  g_xh);
    cudaGetSymbolAddress((void**)&xl,  g_xl);
    cudaGetSymbolAddress((void**)&yht, g_yht);
    cudaGetSymbolAddress((void**)&ylt, g_ylt);
    cudaGetSymbolAddress((void**)&wi,  g_wi);
    cudaGetSymbolAddress((void**)&wg,  g_wg);
    cudaGetSymbolAddress((void**)&wo,  g_wo);

    cudaFuncSetAttribute(proj_kernel,
                         cudaFuncAttributeMaxDynamicSharedMemorySize, GEMM_SMEM);
    cudaFuncSetAttribute(gemm_out_kernel,
                         cudaFuncAttributeMaxDynamicSharedMemorySize, GEMM2_SMEM);
    cudaFuncSetAttribute(scan_kernel,
                         cudaFuncAttributeMaxDynamicSharedMemorySize, SCAN_SMEM);

    param_kernel<<<(DM * SN + 255) / 256, 256>>>(log_A_real, A_imag, B_p, C_p, log_dt);

    const int PREP_N = M_TOT * DM + 3 * DM * DM;
    prep_kernel<<<(PREP_N + 255) / 256, 256>>>(x, W_in, W_gate, W_out,
                                               xh, xl, wi, wg, wo);

    // fused u + gate projections (one well-packed tensor-bound launch)
    proj_kernel<<<512, 256, GEMM_SMEM>>>(xh, xl, wi, wg, pg, b_gate);

    // scan (chain-shortened)
    scan_kernel<<<256, 256, SCAN_SMEM>>>(D_p);

    // out projection, A loaded transposed from g_yht/g_ylt
    gemm_out_kernel<<<dim3(4, M_TOT / GBM), 256, GEMM2_SMEM>>>(yht, ylt, wo,
                                                               out, x, pg);
}

// round 16
// speedup vs baseline: 1.0187x; 1.0187x over previous
#include <cuda_runtime.h>
#include <cuda_bf16.h>
#include <cuda_fp16.h>
#include <cstdint>

#define DM 512
#define SN 64
#define NBATCH 4
#define SEQ 2048
#define M_TOT (NBATCH*SEQ)   // 8192
#define KDIM 512

// ---------------- scratch (no runtime allocation allowed) ----------------
__device__ float g_ut[M_TOT * DM];       // u transposed [b, d, t] (fp32)
__device__ float g_gate[M_TOT * DM];     // sigmoid gate [bt, d]
__device__ __half g_xh[M_TOT * DM];
__device__ __half g_xl[M_TOT * DM];
__device__ __half g_yht[M_TOT * DM];     // y hi, transposed [b, d, t]
__device__ __half g_ylt[M_TOT * DM];     // y lo, transposed
__device__ __half g_wi[DM * DM];
__device__ __half g_wg[DM * DM];
__device__ __half g_wo[DM * DM];
__device__ float g_ar[DM * SN];
__device__ float g_ai[DM * SN];
__device__ float g_cb[DM * SN];

// ---------------- f32x2 packed helpers ------------------------------------
__device__ __forceinline__ unsigned long long pk2(float a, float b) {
    unsigned long long r;
    asm("mov.b64 %0, {%1, %2};" : "=l"(r) : "f"(a), "f"(b));
    return r;
}
__device__ __forceinline__ void upk2(unsigned long long v, float& a, float& b) {
    asm("mov.b64 {%0, %1}, %2;" : "=f"(a), "=f"(b) : "l"(v));
}
__device__ __forceinline__ unsigned long long fma2(unsigned long long a,
                                                   unsigned long long b,
                                                   unsigned long long c) {
    unsigned long long r;
    asm("fma.rn.f32x2 %0, %1, %2, %3;" : "=l"(r) : "l"(a), "l"(b), "l"(c));
    return r;
}
__device__ __forceinline__ unsigned long long mul2(unsigned long long a,
                                                   unsigned long long b) {
    unsigned long long r;
    asm("mul.rn.f32x2 %0, %1, %2;" : "=l"(r) : "l"(a), "l"(b));
    return r;
}
__device__ __forceinline__ unsigned long long add2(unsigned long long a,
                                                   unsigned long long b) {
    unsigned long long r;
    asm("add.rn.f32x2 %0, %1, %2;" : "=l"(r) : "l"(a), "l"(b));
    return r;
}

// ---------------- parameter precompute -----------------------------------
__global__ void param_kernel(const float* __restrict__ log_A_real,
                             const float* __restrict__ A_imag,
                             const float* __restrict__ B_p,
                             const float* __restrict__ C_p,
                             const float* __restrict__ log_dt)
{
    int idx = blockIdx.x * blockDim.x + threadIdx.x;
    if (idx >= DM * SN) return;
    int d = idx / SN;
    float dt  = expf(log_dt[d]);
    float are = -expf(log_A_real[idx]);
    float aim = A_imag[idx];
    float r = expf(are * dt);
    float s, c;
    sincosf(aim * dt, &s, &c);
    g_ar[idx] = r * c;
    g_ai[idx] = r * s;
    g_cb[idx] = C_p[idx] * B_p[idx] * dt;
}

// ---------------- fp32 -> fp16 split of x + fp16 convert of 3 weights ------
__global__ void prep_kernel(const float* __restrict__ x,
                            const float* __restrict__ w0, const float* __restrict__ w1,
                            const float* __restrict__ w2,
                            __half* __restrict__ xh, __half* __restrict__ xl,
                            __half* __restrict__ o0, __half* __restrict__ o1,
                            __half* __restrict__ o2)
{
    int i = blockIdx.x * blockDim.x + threadIdx.x;
    const int NX = M_TOT * DM;
    if (i < NX) {
        float v = x[i];
        __half h = __float2half(v);
        xh[i] = h;
        xl[i] = __float2half(v - __half2float(h));
    } else {
        int j = i - NX;
        if (j >= 3 * DM * DM) return;
        int which = j / (DM * DM);
        int k = j - which * (DM * DM);
        const float* src = (which == 0) ? w0 : (which == 1) ? w1 : w2;
        __half* dst      = (which == 0) ? o0 : (which == 1) ? o1 : o2;
        dst[k] = __float2half(src[k]);
    }
}

// ============================================================================
// fp16 2-pass mma.sync GEMM body (A row-major [m,k] in gmem).
// Tile 128x128, 256 threads (8 warps 2x4), 2-stage.
// MODE 0: u -> written TRANSPOSED to g_ut[b,d,t] via smem.
// MODE 1: sigmoid(acc + bias) -> C.
// ============================================================================
#define GBM 128
#define GBN 128
#define GBK 32
#define RSTRIDE 40
#define PIECE_ELEMS (GBM * RSTRIDE)           // 5120 fp16
#define STAGE_ELEMS (3 * PIECE_ELEMS)         // Ah, Al, B = 15360
#define GEMM_SMEM (2 * STAGE_ELEMS * 2)       // 61440 B
#define SCAN_SMEM (8 * 32 * 36 * 4)           // 36864 B (float partials, v4-aligned)
#define FUSED_SMEM (GEMM_SMEM > SCAN_SMEM ? GEMM_SMEM : SCAN_SMEM)

__device__ __forceinline__ void ldm_x4(uint32_t& r0, uint32_t& r1,
                                       uint32_t& r2, uint32_t& r3, uint32_t addr)
{
    asm volatile("ldmatrix.sync.aligned.m8n8.x4.shared.b16 {%0,%1,%2,%3}, [%4];"
                 : "=r"(r0), "=r"(r1), "=r"(r2), "=r"(r3) : "r"(addr));
}

__device__ __forceinline__ void ldm_x4_t(uint32_t& r0, uint32_t& r1,
                                         uint32_t& r2, uint32_t& r3, uint32_t addr)
{
    asm volatile("ldmatrix.sync.aligned.m8n8.x4.trans.shared.b16 {%0,%1,%2,%3}, [%4];"
                 : "=r"(r0), "=r"(r1), "=r"(r2), "=r"(r3) : "r"(addr));
}

__device__ __forceinline__ void mma16816(float* c, const uint32_t* a,
                                         uint32_t b0, uint32_t b1)
{
    asm volatile(
        "mma.sync.aligned.m16n8k16.row.col.f32.f16.f16.f32 "
        "{%0,%1,%2,%3}, {%4,%5,%6,%7}, {%8,%9}, {%0,%1,%2,%3};"
        : "+f"(c[0]), "+f"(c[1]), "+f"(c[2]), "+f"(c[3])
        : "r"(a[0]), "r"(a[1]), "r"(a[2]), "r"(a[3]), "r"(b0), "r"(b1));
}

#define CP16(dst, src) \
    asm volatile("cp.async.cg.shared.global [%0], [%1], 16;" :: "r"(dst), "l"(src))
#define CP_COMMIT() asm volatile("cp.async.commit_group;")
#define CP_WAIT1()  asm volatile("cp.async.wait_group 1;")
#define CP_WAIT0()  asm volatile("cp.async.wait_group 0;")

template<int MODE>
__device__ __forceinline__ void gemm_body(
    int bx, int by, char* smem_raw,
    const __half* __restrict__ Ah, const __half* __restrict__ Al,
    const __half* __restrict__ B,
    float* __restrict__ C,
    const float* __restrict__ bias)
{
    __half* smem = reinterpret_cast<__half*>(smem_raw);
    const uint32_t sbase = (uint32_t)__cvta_generic_to_shared(smem);

    const int tid  = threadIdx.x;
    const int lane = tid & 31;
    const int warp = tid >> 5;
    const int wm   = warp & 1;
    const int wn   = warp >> 1;
    const int m0   = by * GBM;
    const int n0   = bx * GBN;

    const int arow = tid >> 2;        // 0..63
    const int ac   = (tid & 3) * 8;

    const __half* gAh0 = Ah + (size_t)(m0 + arow)      * KDIM + ac;
    const __half* gAh1 = Ah + (size_t)(m0 + arow + 64) * KDIM + ac;
    const __half* gAl0 = Al + (size_t)(m0 + arow)      * KDIM + ac;
    const __half* gAl1 = Al + (size_t)(m0 + arow + 64) * KDIM + ac;
    const __half* gB0  = B  + (size_t)(n0 + arow)      * KDIM + ac;
    const __half* gB1  = B  + (size_t)(n0 + arow + 64) * KDIM + ac;

    const uint32_t dR0 = (uint32_t)((arow        * RSTRIDE + ac) * 2);
    const uint32_t dR1 = (uint32_t)(((arow + 64) * RSTRIDE + ac) * 2);

    auto load_stage = [&](int s, int kk) {
        uint32_t sb = sbase + (uint32_t)(s * STAGE_ELEMS * 2);
        uint32_t aH = sb;
        uint32_t aL = sb + PIECE_ELEMS * 2;
        uint32_t bB = sb + 2 * PIECE_ELEMS * 2;
        CP16(aH + dR0, gAh0 + kk);
        CP16(aH + dR1, gAh1 + kk);
        CP16(aL + dR0, gAl0 + kk);
        CP16(aL + dR1, gAl1 + kk);
        CP16(bB + dR0, gB0  + kk);
        CP16(bB + dR1, gB1  + kk);
    };

    float acc[4][4][4];
    #pragma unroll
    for (int i = 0; i < 4; i++)
        #pragma unroll
        for (int j = 0; j < 4; j++)
            #pragma unroll
            for (int k = 0; k < 4; k++) acc[i][j][k] = 0.f;

    load_stage(0, 0);   CP_COMMIT();
    load_stage(1, GBK); CP_COMMIT();

    const int grp = lane >> 3;
    const int rin = lane & 7;
    const int rowsel = (grp & 1) * 8 + rin;
    const int colsel = (grp >> 1) * 8;

    const int NKC = KDIM / GBK;        // 16
    for (int kc = 0; kc < NKC; kc++) {
        CP_WAIT1();
        __syncthreads();

        const int s = kc & 1;
        const uint32_t sb = sbase + (uint32_t)(s * STAGE_ELEMS * 2);
        const uint32_t aH = sb;
        const uint32_t aL = sb + PIECE_ELEMS * 2;
        const uint32_t bB = sb + 2 * PIECE_ELEMS * 2;

        #pragma unroll
        for (int ks = 0; ks < 2; ks++) {
            const int kb = ks * 16 + colsel;

            uint32_t bh[2][4];
            #pragma unroll
            for (int p = 0; p < 2; p++) {
                uint32_t off = (uint32_t)(((wn * 32 + p * 16 + rowsel) * RSTRIDE + kb) * 2);
                ldm_x4(bh[p][0], bh[p][1], bh[p][2], bh[p][3], bB + off);
            }

            #pragma unroll
            for (int mt = 0; mt < 4; mt++) {
                uint32_t off = (uint32_t)(((wm * 64 + mt * 16 + rowsel) * RSTRIDE + kb) * 2);
                uint32_t ah[4], al[4];
                ldm_x4(ah[0], ah[1], ah[2], ah[3], aH + off);
                ldm_x4(al[0], al[1], al[2], al[3], aL + off);

                #pragma unroll
                for (int nt = 0; nt < 4; nt++) {
                    const int p = nt >> 1, o = nt & 1;
                    mma16816(acc[mt][nt], ah, bh[p][0 + o], bh[p][2 + o]);
                }
                #pragma unroll
                for (int nt = 0; nt < 4; nt++) {
                    const int p = nt >> 1, o = nt & 1;
                    mma16816(acc[mt][nt], al, bh[p][0 + o], bh[p][2 + o]);
                }
            }
        }
        __syncthreads();
        if (kc + 2 < NKC) load_stage(s, (kc + 2) * GBK);
        CP_COMMIT();
    }

    const int r   = lane >> 2;
    const int cp2 = (lane & 3) * 2;

    if (MODE == 0) {
        // ---- transposed epilogue: u tile -> g_ut[b, d, t] via smem ----
        CP_WAIT0();
        __syncthreads();
        float* tsm = reinterpret_cast<float*>(smem);   // 64 cols x 132 stride
        const int bb = m0 / SEQ;
        const int t0 = m0 % SEQ;
        #pragma unroll
        for (int round = 0; round < 2; round++) {
            if ((wn >> 1) == round) {
                const int colb = (wn & 1) * 32;
                #pragma unroll
                for (int mt = 0; mt < 4; mt++)
                    #pragma unroll
                    for (int nt = 0; nt < 4; nt++)
                        #pragma unroll
                        for (int h = 0; h < 2; h++) {
                            const int row = wm * 64 + mt * 16 + r + h * 8;
                            const int col = colb + nt * 8 + cp2;
                            tsm[col * 132 + row]       = acc[mt][nt][2 * h + 0];
                            tsm[(col + 1) * 132 + row] = acc[mt][nt][2 * h + 1];
                        }
            }
            __syncthreads();
            const int d0r = n0 + round * 64;
            #pragma unroll
            for (int i = 0; i < 8; i++) {
                const int idx = tid + i * 256;
                const int c   = idx >> 5;
                const int tq  = idx & 31;
                float4 v = *(float4*)&tsm[c * 132 + tq * 4];
                *(float4*)&g_ut[(size_t)(bb * DM + d0r + c) * SEQ + t0 + tq * 4] = v;
            }
            __syncthreads();
        }
        return;
    }

    // MODE 1: sigmoid epilogue
    #pragma unroll
    for (int mt = 0; mt < 4; mt++) {
        #pragma unroll
        for (int nt = 0; nt < 4; nt++) {
            const int col  = n0 + wn * 32 + nt * 8 + cp2;
            const int row0 = m0 + wm * 64 + mt * 16 + r;
            #pragma unroll
            for (int h = 0; h < 2; h++) {
                const int row = row0 + h * 8;
                const size_t off = (size_t)row * DM + col;
                float v0 = acc[mt][nt][2 * h + 0];
                float v1 = acc[mt][nt][2 * h + 1];
                v0 = 1.f / (1.f + __expf(-(v0 + bias[col + 0])));
                v1 = 1.f / (1.f + __expf(-(v1 + bias[col + 1])));
                *(float2*)&C[off] = make_float2(v0, v1);
            }
        }
    }
}

// ============================================================================
// out-projection GEMM with A loaded TRANSPOSED from g_yht/g_ylt [b,d,t]
// via ldmatrix.trans — no separate transpose kernel needed.
// ============================================================================
#define RS2 136
#define A2_ELEMS (32 * RS2)                    // 4352
#define STAGE2_ELEMS (2 * A2_ELEMS + PIECE_ELEMS)   // 13824
#define GEMM2_SMEM (2 * STAGE2_ELEMS * 2)      // 55296 B

__global__ __launch_bounds__(256, 2) void gemm_out_kernel(
    const __half* __restrict__ Aht, const __half* __restrict__ Alt,
    const __half* __restrict__ B, float* __restrict__ C,
    const float* __restrict__ xres, const float* __restrict__ gate)
{
    extern __shared__ char dsm[];
    __half* smem = reinterpret_cast<__half*>(dsm);
    const uint32_t sbase = (uint32_t)__cvta_generic_to_shared(smem);

    const int tid  = threadIdx.x;
    const int lane = tid & 31;
    const int warp = tid >> 5;
    const int wm   = warp & 1;
    const int wn   = warp >> 1;
    const int m0   = blockIdx.y * GBM;
    const int n0   = blockIdx.x * GBN;
    const int bb   = m0 / SEQ;
    const int t0   = m0 % SEQ;

    const int r16 = tid >> 4;         // 0..15
    const int c16 = (tid & 15) * 8;   // fp16 offset of 16B chunk
    const int arow = tid >> 2;
    const int ac   = (tid & 3) * 8;
    const __half* gB0 = B + (size_t)(n0 + arow)      * KDIM + ac;
    const __half* gB1 = B + (size_t)(n0 + arow + 64) * KDIM + ac;
    const uint32_t dR0 = (uint32_t)((arow        * RSTRIDE + ac) * 2);
    const uint32_t dR1 = (uint32_t)(((arow + 64) * RSTRIDE + ac) * 2);

    auto load_stage = [&](int s, int kc) {
        const int k0 = kc * GBK;
        uint32_t sb = sbase + (uint32_t)(s * STAGE2_ELEMS * 2);
        uint32_t aH = sb;
        uint32_t aL = sb + A2_ELEMS * 2;
        uint32_t bB = sb + 2 * A2_ELEMS * 2;
        const size_t e0 = (size_t)(bb * DM + k0 + r16)      * SEQ + t0 + c16;
        const size_t e1 = (size_t)(bb * DM + k0 + r16 + 16) * SEQ + t0 + c16;
        CP16(aH + (uint32_t)((r16        * RS2 + c16) * 2), Aht + e0);
        CP16(aH + (uint32_t)(((r16 + 16) * RS2 + c16) * 2), Aht + e1);
        CP16(aL + (uint32_t)((r16        * RS2 + c16) * 2), Alt + e0);
        CP16(aL + (uint32_t)(((r16 + 16) * RS2 + c16) * 2), Alt + e1);
        CP16(bB + dR0, gB0 + k0);
        CP16(bB + dR1, gB1 + k0);
    };

    float acc[4][4][4];
    #pragma unroll
    for (int i = 0; i < 4; i++)
        #pragma unroll
        for (int j = 0; j < 4; j++)
            #pragma unroll
            for (int k = 0; k < 4; k++) acc[i][j][k] = 0.f;

    load_stage(0, 0); CP_COMMIT();
    load_stage(1, 1); CP_COMMIT();

    const int grp = lane >> 3;
    const int rin = lane & 7;
    const int rowsel = (grp & 1) * 8 + rin;
    const int colsel = (grp >> 1) * 8;
    const int akrow = (grp >> 1) * 8 + rin;
    const int amoff = (grp & 1) * 8;

    const int NKC = KDIM / GBK;        // 16
    for (int kc = 0; kc < NKC; kc++) {
        CP_WAIT1();
        __syncthreads();

        const int s = kc & 1;
        const uint32_t sb = sbase + (uint32_t)(s * STAGE2_ELEMS * 2);
        const uint32_t aH = sb;
        const uint32_t aL = sb + A2_ELEMS * 2;
        const uint32_t bB = sb + 2 * A2_ELEMS * 2;

        #pragma unroll
        for (int ks = 0; ks < 2; ks++) {
            const int kb = ks * 16;

            uint32_t bh[2][4];
            #pragma unroll
            for (int p = 0; p < 2; p++) {
                uint32_t off = (uint32_t)(((wn * 32 + p * 16 + rowsel) * RSTRIDE + kb + colsel) * 2);
                ldm_x4(bh[p][0], bh[p][1], bh[p][2], bh[p][3], bB + off);
            }

            #pragma unroll
            for (int mt = 0; mt < 4; mt++) {
                const int mbase = wm * 64 + mt * 16;
                uint32_t off = (uint32_t)(((kb + akrow) * RS2 + mbase + amoff) * 2);
                uint32_t ah[4], al[4];
                ldm_x4_t(ah[0], ah[1], ah[2], ah[3], aH + off);
                ldm_x4_t(al[0], al[1], al[2], al[3], aL + off);

                #pragma unroll
                for (int nt = 0; nt < 4; nt++) {
                    const int p = nt >> 1, o = nt & 1;
                    mma16816(acc[mt][nt], ah, bh[p][0 + o], bh[p][2 + o]);
                }
                #pragma unroll
                for (int nt = 0; nt < 4; nt++) {
                    const int p = nt >> 1, o = nt & 1;
                    mma16816(acc[mt][nt], al, bh[p][0 + o], bh[p][2 + o]);
                }
            }
        }
        __syncthreads();
        if (kc + 2 < NKC) load_stage(s, kc + 2);
        CP_COMMIT();
    }

    const int r   = lane >> 2;
    const int cp2 = (lane & 3) * 2;
    #pragma unroll
    for (int mt = 0; mt < 4; mt++) {
        #pragma unroll
        for (int nt = 0; nt < 4; nt++) {
            const int col  = n0 + wn * 32 + nt * 8 + cp2;
            const int row0 = m0 + wm * 64 + mt * 16 + r;
            #pragma unroll
            for (int h = 0; h < 2; h++) {
                const int row = row0 + h * 8;
                const size_t off = (size_t)row * DM + col;
                float v0 = acc[mt][nt][2 * h + 0];
                float v1 = acc[mt][nt][2 * h + 1];
                float2 xv = *(const float2*)&xres[off];
                float2 gv = *(const float2*)&gate[off];
                v0 = xv.x + gv.x * v0;
                v1 = xv.y + gv.y * v1;
                *(float2*)&C[off] = make_float2(v0, v1);
            }
        }
    }
}

// ---------------- S4D scan body (float partials, vectorized reduction) -----
// Partial row stride = 36 floats: every lane's reduction row is 16B-aligned,
// enabling LDS.128 + packed add2 reduction (8 loads + ~16 adds vs 32+32).
// Write banks (4j+lane) mod 32: conflict-free. LDS.128 phases (8 lanes each)
// cover banks 4L..4L+3 = exactly 0..31: conflict-free.
__device__ __forceinline__ void scan_body(int b, int d,
                                          float* spw,
                                          const float* __restrict__ D_p)
{
    const int lane = threadIdx.x & 31;
    const int base = d * SN;
    const unsigned long long ar2  = pk2(g_ar[base + lane],  g_ar[base + 32 + lane]);
    const unsigned long long ai2  = pk2(g_ai[base + lane],  g_ai[base + 32 + lane]);
    const unsigned long long nai2 = pk2(-g_ai[base + lane], -g_ai[base + 32 + lane]);
    const unsigned long long cb2  = pk2(g_cb[base + lane],  g_cb[base + 32 + lane]);
    const float Dp  = D_p[d];

    const float* up = g_ut + (size_t)(b * DM + d) * SEQ;
    __half* yh = g_yht + (size_t)(b * DM + d) * SEQ;
    __half* yl = g_ylt + (size_t)(b * DM + d) * SEQ;

    unsigned long long gr2 = 0ull, gi2 = 0ull;
    float ucur = up[lane];

    const int NT = SEQ / 32;
    for (int tt = 0; tt < NT; tt++) {
        float unext = 0.f;
        if (tt + 1 < NT) unext = up[(tt + 1) * 32 + lane];

        #pragma unroll
        for (int j = 0; j < 32; j++) {
            float uj = __shfl_sync(0xffffffffu, ucur, j);
            unsigned long long u2  = pk2(uj, uj);
            unsigned long long nr  = fma2(ar2, gr2, fma2(nai2, gi2, mul2(cb2, u2)));
            unsigned long long ni  = fma2(ai2, gr2, mul2(ar2, gi2));
            gr2 = nr; gi2 = ni;
            float s0, s1;
            upk2(nr, s0, s1);
            spw[j * 36 + lane] = s0 + s1;      // scalar partial, STS.32
        }
        __syncwarp();

        // lane L sums 32 floats of row L via 8x LDS.128 + packed add2
        const ulonglong2* rq = (const ulonglong2*)(spw + lane * 36);
        ulonglong2 w0 = rq[0];
        ulonglong2 w1 = rq[1];
        unsigned long long aA = w0.x, aB = w0.y, aC = w1.x, aD = w1.y;
        #pragma unroll
        for (int k2 = 2; k2 < 8; k2 += 2) {
            ulonglong2 wa = rq[k2];
            ulonglong2 wb = rq[k2 + 1];
            aA = add2(aA, wa.x);
            aB = add2(aB, wa.y);
            aC = add2(aC, wb.x);
            aD = add2(aD, wb.y);
        }
        unsigned long long tot = add2(add2(aA, aB), add2(aC, aD));
        float s0, s1;
        upk2(tot, s0, s1);
        float acc = fmaf(Dp, ucur, s0 + s1);

        const int oidx = tt * 32 + lane;
        __half h = __float2half(acc);
        yh[oidx] = h;
        yl[oidx] = __float2half(acc - __half2float(h));
        __syncwarp();

        ucur = unext;
    }
}

// ---------------- kernels --------------------------------------------------
__global__ __launch_bounds__(256, 2) void gemm_u_kernel(
    const __half* __restrict__ Ah, const __half* __restrict__ Al,
    const __half* __restrict__ B)
{
    extern __shared__ char dsm[];
    gemm_body<0>(blockIdx.x, blockIdx.y, dsm, Ah, Al, B, nullptr, nullptr);
}

// Heterogeneous launch, R9/R13 ordering (gate blocks first — measured best).
#define GATE_BLOCKS 256
__global__ __launch_bounds__(256, 2) void gate_scan_kernel(
    const __half* __restrict__ xh, const __half* __restrict__ xl,
    const __half* __restrict__ wg, float* __restrict__ pg,
    const float* __restrict__ bias, const float* __restrict__ D_p)
{
    extern __shared__ char dsm[];
    if (blockIdx.x < GATE_BLOCKS) {
        gemm_body<1>(blockIdx.x & 3, blockIdx.x >> 2, dsm, xh, xl, wg, pg, bias);
    } else {
        const int sidx = blockIdx.x - GATE_BLOCKS;   // 0..255
        const int b  = sidx >> 6;                    // 0..3
        const int d  = (sidx & 63) * 8 + (threadIdx.x >> 5);
        float* spw = reinterpret_cast<float*>(dsm) + (threadIdx.x >> 5) * (32 * 36);
        scan_body(b, d, spw, D_p);
    }
}

// ---------------- launch --------------------------------------------------
extern "C" void kernel_launch(void* const* d_in, const int* in_sizes, int n_in,
                              void* d_out, int out_size)
{
    const float* x          = (const float*)d_in[0];
    const float* log_A_real = (const float*)d_in[1];
    const float* A_imag     = (const float*)d_in[2];
    const float* B_p        = (const float*)d_in[3];
    const float* C_p        = (const float*)d_in[4];
    const float* D_p        = (const float*)d_in[5];
    const float* log_dt     = (const float*)d_in[6];
    const float* W_in       = (const float*)d_in[7];
    const float* W_out      = (const float*)d_in[8];
    const float* W_gate     = (const float*)d_in[9];
    const float* b_gate     = (const float*)d_in[10];
    float* out = (float*)d_out;

    float *pg;
    __half *xh, *xl, *yht, *ylt, *wi, *wg, *wo;
    cudaGetSymbolAddress((void**)&pg,  g_gate);
    cudaGetSymbolAddress((void**)&xh,  g_xh);
    cudaGetSymbolAddress((void**)&xl,  g_xl);
    cudaGetSymbolAddress((void**)&yht, g_yht);
    cudaGetSymbolAddress((void**)&ylt, g_ylt);
    cudaGetSymbolAddress((void**)&wi,  g_wi);
    cudaGetSymbolAddress((void**)&wg,  g_wg);
    cudaGetSymbolAddress((void**)&wo,  g_wo);

    cudaFuncSetAttribute(gemm_u_kernel,
                         cudaFuncAttributeMaxDynamicSharedMemorySize, GEMM_SMEM);
    cudaFuncSetAttribute(gemm_out_kernel,
                         cudaFuncAttributeMaxDynamicSharedMemorySize, GEMM2_SMEM);
    cudaFuncSetAttribute(gate_scan_kernel,
                         cudaFuncAttributeMaxDynamicSharedMemorySize, FUSED_SMEM);

    param_kernel<<<(DM * SN + 255) / 256, 256>>>(log_A_real, A_imag, B_p, C_p, log_dt);

    const int PREP_N = M_TOT * DM + 3 * DM * DM;
    prep_kernel<<<(PREP_N + 255) / 256, 256>>>(x, W_in, W_gate, W_out,
                                               xh, xl, wi, wg, wo);

    // u projection (writes g_ut transposed)
    gemm_u_kernel<<<dim3(4, M_TOT / GBM), 256, GEMM_SMEM>>>(xh, xl, wi);

    // gate GEMM + scan (best measured schedule)
    gate_scan_kernel<<<512, 256, FUSED_SMEM>>>(xh, xl, wg, pg, b_gate, D_p);

    // out projection, A loaded transposed from g_yht/g_ylt
    gemm_out_kernel<<<dim3(4, M_TOT / GBM), 256, GEMM2_SMEM>>>(yht, ylt, wo,
                                                               out, x, pg);
}